// round 7
// baseline (speedup 1.0000x reference)
#include <cuda_runtime.h>
#include <cuda_bf16.h>

#define BN_ 640
#define TSTEPS 127
#define AA_ 6

typedef unsigned long long u64;

// scratch (device global: no allocations allowed)
__device__ float g_state_emb[BN_ * 64];

__device__ __forceinline__ float fsigm(float x) {
    return 1.f / (1.f + expf(-x));
}
__device__ __forceinline__ void fma2(u64& d, u64 a, u64 b) {
    asm("fma.rn.f32x2 %0, %1, %2, %0;" : "+l"(d) : "l"(a), "l"(b));
}
__device__ __forceinline__ float hsum2(u64 v) {
    unsigned lo, hi;
    asm("mov.b64 {%0,%1}, %2;" : "=r"(lo), "=r"(hi) : "l"(v));
    return __uint_as_float(lo) + __uint_as_float(hi);
}

// ---------------------------------------------------------------------------
// Encoder (unchanged): 320 blocks x 256 threads, 2 rows/block.
// ---------------------------------------------------------------------------
__global__ void __launch_bounds__(256) encoder_kernel(
    const float* __restrict__ s_h, const int* __restrict__ a_h,
    const float* __restrict__ w1, const float* __restrict__ b1,
    const float* __restrict__ w2, const float* __restrict__ b2,
    const float* __restrict__ fcw, const float* __restrict__ fcb,
    float* __restrict__ out_masks)
{
    extern __shared__ float esm[];
    float* sw1 = esm;            // 2304
    float* sw2 = sw1 + 2304;     // 9216
    float* s0  = sw2 + 9216;     // 2*512
    float* o1  = s0 + 1024;      // 2*1152
    float* o2  = o1 + 2304;      // 2*512

    int t = threadIdx.x;
    int rbase = blockIdx.x * 2;

    for (int i = t; i < 2304; i += 256) sw1[i] = w1[i];
    for (int i = t; i < 9216; i += 256) sw2[i] = w2[i];
    for (int i = t; i < 1024; i += 256) {
        int rr = i >> 9;
        s0[i] = s_h[(rbase + rr) * 65536 + (i & 511)];
    }
    {
        int rr = t >> 7, tt = t & 127;
        int v = a_h[(rbase + rr) * 128 + tt];
        out_masks[(rbase + rr) * 128 + tt] = (v != (AA_ - 1)) ? 1.f : 0.f;
    }
    __syncthreads();

    for (int task = t; task < 384; task += 256) {
        int rr = task / 192, j = task % 192;
        int oc = j / 6, y = j % 6;
        float bb = b1[oc];
        float acc0 = bb, acc1 = bb, acc2 = bb, acc3 = bb, acc4 = bb, acc5 = bb;
        const float* sin = s0 + rr * 512;
        const float* kpb = sw1 + oc * 72;
        #pragma unroll
        for (int ic = 0; ic < 8; ic++) {
            #pragma unroll
            for (int ky = 0; ky < 3; ky++) {
                const float* ip = sin + ic * 64 + (y + ky) * 8;
                const float* kp = kpb + ic * 9 + ky * 3;
                float k0 = kp[0], k1 = kp[1], k2 = kp[2];
                float i0 = ip[0], i1 = ip[1], i2 = ip[2], i3 = ip[3];
                float i4 = ip[4], i5 = ip[5], i6 = ip[6], i7 = ip[7];
                acc0 += i0 * k0 + i1 * k1 + i2 * k2;
                acc1 += i1 * k0 + i2 * k1 + i3 * k2;
                acc2 += i2 * k0 + i3 * k1 + i4 * k2;
                acc3 += i3 * k0 + i4 * k1 + i5 * k2;
                acc4 += i4 * k0 + i5 * k1 + i6 * k2;
                acc5 += i5 * k0 + i6 * k1 + i7 * k2;
            }
        }
        float* op = o1 + rr * 1152 + oc * 36 + y * 6;
        op[0] = fmaxf(acc0, 0.f); op[1] = fmaxf(acc1, 0.f);
        op[2] = fmaxf(acc2, 0.f); op[3] = fmaxf(acc3, 0.f);
        op[4] = fmaxf(acc4, 0.f); op[5] = fmaxf(acc5, 0.f);
    }
    __syncthreads();

    {
        int task = t;
        int rr = task >> 7, j = task & 127;
        int oc = j >> 2, y = j & 3;
        float bb = b2[oc];
        float acc0 = bb, acc1 = bb, acc2 = bb, acc3 = bb;
        const float* iin = o1 + rr * 1152;
        const float* kpb = sw2 + oc * 288;
        #pragma unroll 4
        for (int ic = 0; ic < 32; ic++) {
            #pragma unroll
            for (int ky = 0; ky < 3; ky++) {
                const float* ip = iin + ic * 36 + (y + ky) * 6;
                const float* kp = kpb + ic * 9 + ky * 3;
                float k0 = kp[0], k1 = kp[1], k2 = kp[2];
                float i0 = ip[0], i1 = ip[1], i2 = ip[2];
                float i3 = ip[3], i4 = ip[4], i5 = ip[5];
                acc0 += i0 * k0 + i1 * k1 + i2 * k2;
                acc1 += i1 * k0 + i2 * k1 + i3 * k2;
                acc2 += i2 * k0 + i3 * k1 + i4 * k2;
                acc3 += i3 * k0 + i4 * k1 + i5 * k2;
            }
        }
        float* op = o2 + rr * 512 + oc * 16 + y * 4;
        op[0] = fmaxf(acc0, 0.f); op[1] = fmaxf(acc1, 0.f);
        op[2] = fmaxf(acc2, 0.f); op[3] = fmaxf(acc3, 0.f);
    }
    __syncthreads();

    int w = t >> 5, lane = t & 31;
    for (int task = w; task < 128; task += 8) {
        int rr = task >> 6, o = task & 63;
        const float4* wp = (const float4*)(fcw + o * 512);
        const float4* xp = (const float4*)(o2 + rr * 512);
        float acc = 0.f;
        #pragma unroll
        for (int i = 0; i < 4; i++) {
            float4 a = wp[lane + 32 * i];
            float4 b = xp[lane + 32 * i];
            acc += a.x * b.x + a.y * b.y + a.z * b.z + a.w * b.w;
        }
        #pragma unroll
        for (int d = 16; d > 0; d >>= 1)
            acc += __shfl_xor_sync(0xffffffffu, acc, d);
        if (lane == 0)
            g_state_emb[(rbase + rr) * 64 + o] = fmaxf(acc + fcb[o], 0.f);
    }
}

// ---------------------------------------------------------------------------
// Recurrent rollout v5: 128 blocks x 320 threads, 5 rows/block (single wave,
// no SM imbalance). Weights in registers.
//   t in [0,192)   : GRU dot row o=t        (Whh row in 32 regs)
//   t in [192,256) : mlp1 dot d=t-192       (m1w row in 32 regs)   warps 6,7
//   t in [256,288) : mlp2+argmax, 30 lanes  (m2w row in 32 regs)   warp 8
//   t in [288,320) : idle in dot phase                              warp 9
// Pointwise: all 320 threads, (pr=t/64 in 0..4, pd=t%64).
// Warps 6,7,8 sync via named barrier 1 (96 threads).
// ---------------------------------------------------------------------------
__global__ void __launch_bounds__(320) recur_kernel(
    const float* __restrict__ b_z, const float* __restrict__ emb,
    const float* __restrict__ wih, const float* __restrict__ whh,
    const float* __restrict__ bih, const float* __restrict__ bhh_g,
    const float* __restrict__ m1w, const float* __restrict__ m1b,
    const float* __restrict__ m2w, const float* __restrict__ m2b,
    float* __restrict__ out_logits)
{
    __shared__ __align__(16) float AT[6 * 208];   // act table
    __shared__ __align__(16) float GH[5 * 192];   // gh exchange
    __shared__ __align__(16) float HN[5 * 68];    // h state (68 = 17 u64x2)
    __shared__ __align__(16) float HID[5 * 68];   // hid exchange
    __shared__ __align__(16) float XV[5 * 128];   // [se|bz] preamble
    __shared__ float LG[5 * 8];                   // logits for argmax scan
    __shared__ int ACTS[5];

    int t = threadIdx.x;
    int rbase = blockIdx.x * 5;
    int pr = t >> 6, pd = t & 63;                  // pointwise role

    // ---- stage small tables ----
    for (int idx = t; idx < 6 * 192; idx += 320) {
        int a = idx / 192, o = idx % 192;
        float sum = 0.f;
        #pragma unroll
        for (int j = 0; j < 6; j++) sum += emb[a * 6 + j] * wih[o * 134 + 64 + j];
        AT[a * 208 + o] = sum;
    }
    for (int i = t; i < 5 * 128; i += 320) {
        int rr = i >> 7, k = i & 127;
        XV[rr * 128 + k] = (k < 64) ? g_state_emb[(rbase + rr) * 64 + k]
                                    : b_z[((rbase + rr) / 10) * 64 + (k - 64)];
    }
    if (t < 5 * 68) HN[t] = 0.f;        // fresh h each launch (graph-safe)
    if (t < 5) ACTS[t] = AA_ - 1;
    __syncthreads();

    // ---- pointwise preamble: base gx (x-part + bih) for (pr, pd) ----
    float bg0 = bih[pd], bg1 = bih[64 + pd], bg2 = bih[128 + pd];
    {
        const float* xv = XV + pr * 128;
        const float* w0 = wih + pd * 134;
        const float* w1r = wih + (64 + pd) * 134;
        const float* w2r = wih + (128 + pd) * 134;
        for (int k = 0; k < 64; k++) {
            float x = xv[k];
            bg0 += x * w0[k]; bg1 += x * w1r[k]; bg2 += x * w2r[k];
        }
        for (int k = 0; k < 64; k++) {
            float x = xv[64 + k];
            bg0 += x * w0[70 + k]; bg1 += x * w1r[70 + k]; bg2 += x * w2r[70 + k];
        }
    }
    float hreg = 0.f;

    // ---- dot-role weights into registers (once) ----
    int m2idx = t - 256;                  // warp-8 task index
    int r2 = m2idx / 6, a2 = m2idx - r2 * 6;
    bool m2v = (t >= 256 && m2idx < 30);

    ulonglong2 wq[16];
    float dbias = 0.f;
    if (t < 192) {
        const ulonglong2* wp = (const ulonglong2*)(whh + t * 64);
        #pragma unroll
        for (int j = 0; j < 16; j++) wq[j] = wp[j];
        dbias = bhh_g[t];
    } else if (t < 256) {
        const ulonglong2* wp = (const ulonglong2*)(m1w + (t - 192) * 64);
        #pragma unroll
        for (int j = 0; j < 16; j++) wq[j] = wp[j];
        dbias = m1b[t - 192];
    } else if (m2v) {
        const ulonglong2* wp = (const ulonglong2*)(m2w + a2 * 64);
        #pragma unroll
        for (int j = 0; j < 16; j++) wq[j] = wp[j];
        dbias = m2b[a2];
    }

    float* outp = out_logits;

    for (int i = 0; i <= TSTEPS; i++) {
        __syncthreads();   // h_new(i-1) settled, ACTS(i-2) consumed

        if (t < 192) {
            if (i < TSTEPS) {
                // GRU dot: row o=t over 5 rows, h uniform loads
                u64 a0 = 0ull, a1 = 0ull, a2a = 0ull, a3 = 0ull, a4 = 0ull;
                const ulonglong2* hq = (const ulonglong2*)HN;
                #pragma unroll
                for (int k4 = 0; k4 < 16; k4++) {
                    ulonglong2 x0 = hq[k4];
                    ulonglong2 x1 = hq[17 + k4];
                    ulonglong2 x2 = hq[34 + k4];
                    ulonglong2 x3 = hq[51 + k4];
                    ulonglong2 x4 = hq[68 + k4];
                    u64 wl = wq[k4].x, wh = wq[k4].y;
                    fma2(a0, x0.x, wl); fma2(a0, x0.y, wh);
                    fma2(a1, x1.x, wl); fma2(a1, x1.y, wh);
                    fma2(a2a, x2.x, wl); fma2(a2a, x2.y, wh);
                    fma2(a3, x3.x, wl); fma2(a3, x3.y, wh);
                    fma2(a4, x4.x, wl); fma2(a4, x4.y, wh);
                }
                GH[0 * 192 + t] = hsum2(a0) + dbias;
                GH[1 * 192 + t] = hsum2(a1) + dbias;
                GH[2 * 192 + t] = hsum2(a2a) + dbias;
                GH[3 * 192 + t] = hsum2(a3) + dbias;
                GH[4 * 192 + t] = hsum2(a4) + dbias;
            }
        } else if (t < 288) {
            // warps 6,7: mlp1 for step i-1; warp 8: mlp2+argmax after bar.sync
            if (t < 256 && i > 0) {
                int d = t - 192;
                u64 a0 = 0ull, a1 = 0ull, a2a = 0ull, a3 = 0ull, a4 = 0ull;
                const ulonglong2* hq = (const ulonglong2*)HN;
                #pragma unroll
                for (int k4 = 0; k4 < 16; k4++) {
                    ulonglong2 x0 = hq[k4];
                    ulonglong2 x1 = hq[17 + k4];
                    ulonglong2 x2 = hq[34 + k4];
                    ulonglong2 x3 = hq[51 + k4];
                    ulonglong2 x4 = hq[68 + k4];
                    u64 wl = wq[k4].x, wh = wq[k4].y;
                    fma2(a0, x0.x, wl); fma2(a0, x0.y, wh);
                    fma2(a1, x1.x, wl); fma2(a1, x1.y, wh);
                    fma2(a2a, x2.x, wl); fma2(a2a, x2.y, wh);
                    fma2(a3, x3.x, wl); fma2(a3, x3.y, wh);
                    fma2(a4, x4.x, wl); fma2(a4, x4.y, wh);
                }
                HID[0 * 68 + d] = tanhf(hsum2(a0) + dbias);
                HID[1 * 68 + d] = tanhf(hsum2(a1) + dbias);
                HID[2 * 68 + d] = tanhf(hsum2(a2a) + dbias);
                HID[3 * 68 + d] = tanhf(hsum2(a3) + dbias);
                HID[4 * 68 + d] = tanhf(hsum2(a4) + dbias);
            }
            asm volatile("bar.sync 1, 96;" ::: "memory");  // warps 6,7,8
            if (t >= 256) {
                if (i > 0) {
                    if (m2v) {
                        u64 al = 0ull, bl = 0ull;
                        const ulonglong2* hh = (const ulonglong2*)(HID + r2 * 68);
                        #pragma unroll
                        for (int k4 = 0; k4 < 16; k4 += 2) {
                            ulonglong2 h0 = hh[k4], h1 = hh[k4 + 1];
                            fma2(al, h0.x, wq[k4].x); fma2(al, h0.y, wq[k4].y);
                            fma2(bl, h1.x, wq[k4 + 1].x); fma2(bl, h1.y, wq[k4 + 1].y);
                        }
                        float lacc = hsum2(al) + hsum2(bl) + dbias;
                        outp[((rbase + r2) * TSTEPS + (i - 1)) * 6 + a2] = lacc;
                        LG[r2 * 8 + a2] = lacc;
                    }
                    __syncwarp();
                    if (m2idx < 5) {           // one lane per row: first-max scan
                        const float* lg = LG + m2idx * 8;
                        float bv = lg[0]; int bi = 0;
                        #pragma unroll
                        for (int a = 1; a < 6; a++) {
                            float v = lg[a];
                            if (v > bv) { bv = v; bi = a; }
                        }
                        ACTS[m2idx] = bi;
                    }
                }
            }
        }
        __syncthreads();   // gh(i) + ACTS(i-1) visible

        if (i < TSTEPS) {
            float ghr = GH[pr * 192 + pd];
            float ghz = GH[pr * 192 + 64 + pd];
            float ghn = GH[pr * 192 + 128 + pd];
            const float* atr = AT + ACTS[pr] * 208;
            float rg = fsigm(bg0 + atr[pd] + ghr);
            float zg = fsigm(bg1 + atr[64 + pd] + ghz);
            float ng = tanhf(bg2 + atr[128 + pd] + rg * ghn);
            hreg = (1.f - zg) * ng + zg * hreg;
            HN[pr * 68 + pd] = hreg;
        }
    }
}

extern "C" void kernel_launch(void* const* d_in, const int* in_sizes, int n_in,
                              void* d_out, int out_size) {
    const float* s_h = (const float*)d_in[0];
    const int*   a_h = (const int*)  d_in[1];
    const float* b_z = (const float*)d_in[2];
    const float* w1  = (const float*)d_in[3];
    const float* b1  = (const float*)d_in[4];
    const float* w2  = (const float*)d_in[5];
    const float* b2  = (const float*)d_in[6];
    const float* fcw = (const float*)d_in[7];
    const float* fcb = (const float*)d_in[8];
    const float* emb = (const float*)d_in[9];
    const float* wih = (const float*)d_in[10];
    const float* whh = (const float*)d_in[11];
    const float* bih = (const float*)d_in[12];
    const float* bhh = (const float*)d_in[13];
    const float* m1w = (const float*)d_in[14];
    const float* m1b = (const float*)d_in[15];
    const float* m2w = (const float*)d_in[16];
    const float* m2b = (const float*)d_in[17];

    float* out = (float*)d_out;
    float* out_logits = out;                       // [B,N,T-1,A]
    float* out_masks  = out + BN_ * TSTEPS * AA_;  // [B,N,T,1]

    static const size_t ENC_SMEM = 15872 * sizeof(float);   // ~63.5 KB
    cudaFuncSetAttribute(encoder_kernel,
                         cudaFuncAttributeMaxDynamicSharedMemorySize,
                         (int)ENC_SMEM);

    encoder_kernel<<<320, 256, ENC_SMEM>>>(s_h, a_h, w1, b1, w2, b2,
                                           fcw, fcb, out_masks);
    recur_kernel<<<128, 320>>>(b_z, emb, wih, whh, bih, bhh,
                               m1w, m1b, m2w, m2b, out_logits);
}

// round 8
// speedup vs baseline: 2.0465x; 2.0465x over previous
#include <cuda_runtime.h>
#include <cuda_bf16.h>

#define BN_ 640
#define TSTEPS 127
#define AA_ 6

typedef unsigned long long u64;

// scratch (device global: no allocations allowed)
__device__ float g_state_emb[BN_ * 64];

__device__ __forceinline__ float fsigm(float x) {
    return 1.f / (1.f + expf(-x));
}
__device__ __forceinline__ void fma2(u64& d, u64 a, u64 b) {
    asm("fma.rn.f32x2 %0, %1, %2, %0;" : "+l"(d) : "l"(a), "l"(b));
}
__device__ __forceinline__ float hsum2(u64 v) {
    unsigned lo, hi;
    asm("mov.b64 {%0,%1}, %2;" : "=r"(lo), "=r"(hi) : "l"(v));
    return __uint_as_float(lo) + __uint_as_float(hi);
}

// ---------------------------------------------------------------------------
// Encoder (unchanged): 320 blocks x 256 threads, 2 rows/block.
// ---------------------------------------------------------------------------
__global__ void __launch_bounds__(256) encoder_kernel(
    const float* __restrict__ s_h, const int* __restrict__ a_h,
    const float* __restrict__ w1, const float* __restrict__ b1,
    const float* __restrict__ w2, const float* __restrict__ b2,
    const float* __restrict__ fcw, const float* __restrict__ fcb,
    float* __restrict__ out_masks)
{
    extern __shared__ float esm[];
    float* sw1 = esm;            // 2304
    float* sw2 = sw1 + 2304;     // 9216
    float* s0  = sw2 + 9216;     // 2*512
    float* o1  = s0 + 1024;      // 2*1152
    float* o2  = o1 + 2304;      // 2*512

    int t = threadIdx.x;
    int rbase = blockIdx.x * 2;

    for (int i = t; i < 2304; i += 256) sw1[i] = w1[i];
    for (int i = t; i < 9216; i += 256) sw2[i] = w2[i];
    for (int i = t; i < 1024; i += 256) {
        int rr = i >> 9;
        s0[i] = s_h[(rbase + rr) * 65536 + (i & 511)];
    }
    {
        int rr = t >> 7, tt = t & 127;
        int v = a_h[(rbase + rr) * 128 + tt];
        out_masks[(rbase + rr) * 128 + tt] = (v != (AA_ - 1)) ? 1.f : 0.f;
    }
    __syncthreads();

    for (int task = t; task < 384; task += 256) {
        int rr = task / 192, j = task % 192;
        int oc = j / 6, y = j % 6;
        float bb = b1[oc];
        float acc0 = bb, acc1 = bb, acc2 = bb, acc3 = bb, acc4 = bb, acc5 = bb;
        const float* sin = s0 + rr * 512;
        const float* kpb = sw1 + oc * 72;
        #pragma unroll
        for (int ic = 0; ic < 8; ic++) {
            #pragma unroll
            for (int ky = 0; ky < 3; ky++) {
                const float* ip = sin + ic * 64 + (y + ky) * 8;
                const float* kp = kpb + ic * 9 + ky * 3;
                float k0 = kp[0], k1 = kp[1], k2 = kp[2];
                float i0 = ip[0], i1 = ip[1], i2 = ip[2], i3 = ip[3];
                float i4 = ip[4], i5 = ip[5], i6 = ip[6], i7 = ip[7];
                acc0 += i0 * k0 + i1 * k1 + i2 * k2;
                acc1 += i1 * k0 + i2 * k1 + i3 * k2;
                acc2 += i2 * k0 + i3 * k1 + i4 * k2;
                acc3 += i3 * k0 + i4 * k1 + i5 * k2;
                acc4 += i4 * k0 + i5 * k1 + i6 * k2;
                acc5 += i5 * k0 + i6 * k1 + i7 * k2;
            }
        }
        float* op = o1 + rr * 1152 + oc * 36 + y * 6;
        op[0] = fmaxf(acc0, 0.f); op[1] = fmaxf(acc1, 0.f);
        op[2] = fmaxf(acc2, 0.f); op[3] = fmaxf(acc3, 0.f);
        op[4] = fmaxf(acc4, 0.f); op[5] = fmaxf(acc5, 0.f);
    }
    __syncthreads();

    {
        int task = t;
        int rr = task >> 7, j = task & 127;
        int oc = j >> 2, y = j & 3;
        float bb = b2[oc];
        float acc0 = bb, acc1 = bb, acc2 = bb, acc3 = bb;
        const float* iin = o1 + rr * 1152;
        const float* kpb = sw2 + oc * 288;
        #pragma unroll 4
        for (int ic = 0; ic < 32; ic++) {
            #pragma unroll
            for (int ky = 0; ky < 3; ky++) {
                const float* ip = iin + ic * 36 + (y + ky) * 6;
                const float* kp = kpb + ic * 9 + ky * 3;
                float k0 = kp[0], k1 = kp[1], k2 = kp[2];
                float i0 = ip[0], i1 = ip[1], i2 = ip[2];
                float i3 = ip[3], i4 = ip[4], i5 = ip[5];
                acc0 += i0 * k0 + i1 * k1 + i2 * k2;
                acc1 += i1 * k0 + i2 * k1 + i3 * k2;
                acc2 += i2 * k0 + i3 * k1 + i4 * k2;
                acc3 += i3 * k0 + i4 * k1 + i5 * k2;
            }
        }
        float* op = o2 + rr * 512 + oc * 16 + y * 4;
        op[0] = fmaxf(acc0, 0.f); op[1] = fmaxf(acc1, 0.f);
        op[2] = fmaxf(acc2, 0.f); op[3] = fmaxf(acc3, 0.f);
    }
    __syncthreads();

    int w = t >> 5, lane = t & 31;
    for (int task = w; task < 128; task += 8) {
        int rr = task >> 6, o = task & 63;
        const float4* wp = (const float4*)(fcw + o * 512);
        const float4* xp = (const float4*)(o2 + rr * 512);
        float acc = 0.f;
        #pragma unroll
        for (int i = 0; i < 4; i++) {
            float4 a = wp[lane + 32 * i];
            float4 b = xp[lane + 32 * i];
            acc += a.x * b.x + a.y * b.y + a.z * b.z + a.w * b.w;
        }
        #pragma unroll
        for (int d = 16; d > 0; d >>= 1)
            acc += __shfl_xor_sync(0xffffffffu, acc, d);
        if (lane == 0)
            g_state_emb[(rbase + rr) * 64 + o] = fmaxf(acc + fcb[o], 0.f);
    }
}

// ---------------------------------------------------------------------------
// Recurrent rollout v6 = v5 + __launch_bounds__(320, 1).
// R7's regression was ptxas capping at 99 regs (default 2-block occupancy
// target for 320 threads) and spilling the 32-reg weight array to local.
// minBlocks=1 lifts the cap to 204 regs -> weights stay register-resident.
// 128 blocks x 320 threads, 5 rows/block (single wave, no SM imbalance).
//   t in [0,192)   : GRU dot row o=t        (Whh row in 32 regs)
//   t in [192,256) : mlp1 dot d=t-192       (m1w row in 32 regs)   warps 6,7
//   t in [256,288) : mlp2+argmax, 30 lanes  (m2w row in 32 regs)   warp 8
//   t in [288,320) : idle in dot phase                              warp 9
// Pointwise: all 320 threads, (pr=t/64 in 0..4, pd=t%64).
// Warps 6,7,8 sync via named barrier 1 (96 threads).
// ---------------------------------------------------------------------------
__global__ void __launch_bounds__(320, 1) recur_kernel(
    const float* __restrict__ b_z, const float* __restrict__ emb,
    const float* __restrict__ wih, const float* __restrict__ whh,
    const float* __restrict__ bih, const float* __restrict__ bhh_g,
    const float* __restrict__ m1w, const float* __restrict__ m1b,
    const float* __restrict__ m2w, const float* __restrict__ m2b,
    float* __restrict__ out_logits)
{
    __shared__ __align__(16) float AT[6 * 208];   // act table
    __shared__ __align__(16) float GH[5 * 192];   // gh exchange
    __shared__ __align__(16) float HN[5 * 68];    // h state (68 = 17 u64x2)
    __shared__ __align__(16) float HID[5 * 68];   // hid exchange
    __shared__ __align__(16) float XV[5 * 128];   // [se|bz] preamble
    __shared__ float LG[5 * 8];                   // logits for argmax scan
    __shared__ int ACTS[5];

    int t = threadIdx.x;
    int rbase = blockIdx.x * 5;
    int pr = t >> 6, pd = t & 63;                  // pointwise role

    // ---- stage small tables ----
    for (int idx = t; idx < 6 * 192; idx += 320) {
        int a = idx / 192, o = idx % 192;
        float sum = 0.f;
        #pragma unroll
        for (int j = 0; j < 6; j++) sum += emb[a * 6 + j] * wih[o * 134 + 64 + j];
        AT[a * 208 + o] = sum;
    }
    for (int i = t; i < 5 * 128; i += 320) {
        int rr = i >> 7, k = i & 127;
        XV[rr * 128 + k] = (k < 64) ? g_state_emb[(rbase + rr) * 64 + k]
                                    : b_z[((rbase + rr) / 10) * 64 + (k - 64)];
    }
    if (t < 5 * 68) HN[t] = 0.f;        // fresh h each launch (graph-safe)
    if (t < 5) ACTS[t] = AA_ - 1;
    __syncthreads();

    // ---- pointwise preamble: base gx (x-part + bih) for (pr, pd) ----
    float bg0 = bih[pd], bg1 = bih[64 + pd], bg2 = bih[128 + pd];
    {
        const float* xv = XV + pr * 128;
        const float* w0 = wih + pd * 134;
        const float* w1r = wih + (64 + pd) * 134;
        const float* w2r = wih + (128 + pd) * 134;
        for (int k = 0; k < 64; k++) {
            float x = xv[k];
            bg0 += x * w0[k]; bg1 += x * w1r[k]; bg2 += x * w2r[k];
        }
        for (int k = 0; k < 64; k++) {
            float x = xv[64 + k];
            bg0 += x * w0[70 + k]; bg1 += x * w1r[70 + k]; bg2 += x * w2r[70 + k];
        }
    }
    float hreg = 0.f;

    // ---- dot-role weights into registers (once) ----
    int m2idx = t - 256;                  // warp-8 task index
    int r2 = m2idx / 6, a2 = m2idx - r2 * 6;
    bool m2v = (t >= 256 && m2idx < 30);

    ulonglong2 wq[16];
    float dbias = 0.f;
    if (t < 192) {
        const ulonglong2* wp = (const ulonglong2*)(whh + t * 64);
        #pragma unroll
        for (int j = 0; j < 16; j++) wq[j] = wp[j];
        dbias = bhh_g[t];
    } else if (t < 256) {
        const ulonglong2* wp = (const ulonglong2*)(m1w + (t - 192) * 64);
        #pragma unroll
        for (int j = 0; j < 16; j++) wq[j] = wp[j];
        dbias = m1b[t - 192];
    } else if (m2v) {
        const ulonglong2* wp = (const ulonglong2*)(m2w + a2 * 64);
        #pragma unroll
        for (int j = 0; j < 16; j++) wq[j] = wp[j];
        dbias = m2b[a2];
    }

    float* outp = out_logits;

    for (int i = 0; i <= TSTEPS; i++) {
        __syncthreads();   // h_new(i-1) settled, ACTS(i-2) consumed

        if (t < 192) {
            if (i < TSTEPS) {
                // GRU dot: row o=t over 5 rows, h uniform loads
                u64 a0 = 0ull, a1 = 0ull, a2a = 0ull, a3 = 0ull, a4 = 0ull;
                const ulonglong2* hq = (const ulonglong2*)HN;
                #pragma unroll
                for (int k4 = 0; k4 < 16; k4++) {
                    ulonglong2 x0 = hq[k4];
                    ulonglong2 x1 = hq[17 + k4];
                    ulonglong2 x2 = hq[34 + k4];
                    ulonglong2 x3 = hq[51 + k4];
                    ulonglong2 x4 = hq[68 + k4];
                    u64 wl = wq[k4].x, wh = wq[k4].y;
                    fma2(a0, x0.x, wl); fma2(a0, x0.y, wh);
                    fma2(a1, x1.x, wl); fma2(a1, x1.y, wh);
                    fma2(a2a, x2.x, wl); fma2(a2a, x2.y, wh);
                    fma2(a3, x3.x, wl); fma2(a3, x3.y, wh);
                    fma2(a4, x4.x, wl); fma2(a4, x4.y, wh);
                }
                GH[0 * 192 + t] = hsum2(a0) + dbias;
                GH[1 * 192 + t] = hsum2(a1) + dbias;
                GH[2 * 192 + t] = hsum2(a2a) + dbias;
                GH[3 * 192 + t] = hsum2(a3) + dbias;
                GH[4 * 192 + t] = hsum2(a4) + dbias;
            }
        } else if (t < 288) {
            // warps 6,7: mlp1 for step i-1; warp 8: mlp2+argmax after bar.sync
            if (t < 256 && i > 0) {
                int d = t - 192;
                u64 a0 = 0ull, a1 = 0ull, a2a = 0ull, a3 = 0ull, a4 = 0ull;
                const ulonglong2* hq = (const ulonglong2*)HN;
                #pragma unroll
                for (int k4 = 0; k4 < 16; k4++) {
                    ulonglong2 x0 = hq[k4];
                    ulonglong2 x1 = hq[17 + k4];
                    ulonglong2 x2 = hq[34 + k4];
                    ulonglong2 x3 = hq[51 + k4];
                    ulonglong2 x4 = hq[68 + k4];
                    u64 wl = wq[k4].x, wh = wq[k4].y;
                    fma2(a0, x0.x, wl); fma2(a0, x0.y, wh);
                    fma2(a1, x1.x, wl); fma2(a1, x1.y, wh);
                    fma2(a2a, x2.x, wl); fma2(a2a, x2.y, wh);
                    fma2(a3, x3.x, wl); fma2(a3, x3.y, wh);
                    fma2(a4, x4.x, wl); fma2(a4, x4.y, wh);
                }
                HID[0 * 68 + d] = tanhf(hsum2(a0) + dbias);
                HID[1 * 68 + d] = tanhf(hsum2(a1) + dbias);
                HID[2 * 68 + d] = tanhf(hsum2(a2a) + dbias);
                HID[3 * 68 + d] = tanhf(hsum2(a3) + dbias);
                HID[4 * 68 + d] = tanhf(hsum2(a4) + dbias);
            }
            asm volatile("bar.sync 1, 96;" ::: "memory");  // warps 6,7,8
            if (t >= 256) {
                if (i > 0) {
                    if (m2v) {
                        u64 al = 0ull, bl = 0ull;
                        const ulonglong2* hh = (const ulonglong2*)(HID + r2 * 68);
                        #pragma unroll
                        for (int k4 = 0; k4 < 16; k4 += 2) {
                            ulonglong2 h0 = hh[k4], h1 = hh[k4 + 1];
                            fma2(al, h0.x, wq[k4].x); fma2(al, h0.y, wq[k4].y);
                            fma2(bl, h1.x, wq[k4 + 1].x); fma2(bl, h1.y, wq[k4 + 1].y);
                        }
                        float lacc = hsum2(al) + hsum2(bl) + dbias;
                        outp[((rbase + r2) * TSTEPS + (i - 1)) * 6 + a2] = lacc;
                        LG[r2 * 8 + a2] = lacc;
                    }
                    __syncwarp();
                    if (m2idx < 5) {           // one lane per row: first-max scan
                        const float* lg = LG + m2idx * 8;
                        float bv = lg[0]; int bi = 0;
                        #pragma unroll
                        for (int a = 1; a < 6; a++) {
                            float v = lg[a];
                            if (v > bv) { bv = v; bi = a; }
                        }
                        ACTS[m2idx] = bi;
                    }
                }
            }
        }
        __syncthreads();   // gh(i) + ACTS(i-1) visible

        if (i < TSTEPS) {
            float ghr = GH[pr * 192 + pd];
            float ghz = GH[pr * 192 + 64 + pd];
            float ghn = GH[pr * 192 + 128 + pd];
            const float* atr = AT + ACTS[pr] * 208;
            float rg = fsigm(bg0 + atr[pd] + ghr);
            float zg = fsigm(bg1 + atr[64 + pd] + ghz);
            float ng = tanhf(bg2 + atr[128 + pd] + rg * ghn);
            hreg = (1.f - zg) * ng + zg * hreg;
            HN[pr * 68 + pd] = hreg;
        }
    }
}

extern "C" void kernel_launch(void* const* d_in, const int* in_sizes, int n_in,
                              void* d_out, int out_size) {
    const float* s_h = (const float*)d_in[0];
    const int*   a_h = (const int*)  d_in[1];
    const float* b_z = (const float*)d_in[2];
    const float* w1  = (const float*)d_in[3];
    const float* b1  = (const float*)d_in[4];
    const float* w2  = (const float*)d_in[5];
    const float* b2  = (const float*)d_in[6];
    const float* fcw = (const float*)d_in[7];
    const float* fcb = (const float*)d_in[8];
    const float* emb = (const float*)d_in[9];
    const float* wih = (const float*)d_in[10];
    const float* whh = (const float*)d_in[11];
    const float* bih = (const float*)d_in[12];
    const float* bhh = (const float*)d_in[13];
    const float* m1w = (const float*)d_in[14];
    const float* m1b = (const float*)d_in[15];
    const float* m2w = (const float*)d_in[16];
    const float* m2b = (const float*)d_in[17];

    float* out = (float*)d_out;
    float* out_logits = out;                       // [B,N,T-1,A]
    float* out_masks  = out + BN_ * TSTEPS * AA_;  // [B,N,T,1]

    static const size_t ENC_SMEM = 15872 * sizeof(float);   // ~63.5 KB
    cudaFuncSetAttribute(encoder_kernel,
                         cudaFuncAttributeMaxDynamicSharedMemorySize,
                         (int)ENC_SMEM);

    encoder_kernel<<<320, 256, ENC_SMEM>>>(s_h, a_h, w1, b1, w2, b2,
                                           fcw, fcb, out_masks);
    recur_kernel<<<128, 320>>>(b_z, emb, wih, whh, bih, bhh,
                               m1w, m1b, m2w, m2b, out_logits);
}